// round 2
// baseline (speedup 1.0000x reference)
#include <cuda_runtime.h>
#include <cuda_bf16.h>

// TRM_57286273794231: B independent rows, each iterating a tiny 12->4 tanh MLP
// 16*(6+1) times, then decode (y_hat) + sigmoid q-head.
//
// Key reductions:
//  * Wy is dead (ys starts at zero -> ys_e = by).
//  * xs_e contribution to the net pre-activation is loop-invariant  -> prex[4].
//  * ye contribution is invariant across the 6 inner z-steps        -> yep[4].
//  * tanh computed as 1 - 2*rcp(1 + ex2(s')) with the 2*log2(e) factor folded
//    into the Wnet/bnet register copies (2 MUFU + 1 FADD + 1 FMA per tanh,
//    ~1e-6 accuracy).

#define T_ITERS 16
#define N_ITERS 6

__device__ __forceinline__ float ex2f(float x) {
    float r; asm("ex2.approx.f32 %0, %1;" : "=f"(r) : "f"(x)); return r;
}
__device__ __forceinline__ float rcpf(float x) {
    float r; asm("rcp.approx.f32 %0, %1;" : "=f"(r) : "f"(x)); return r;
}

// tanh(s) given sp = (2*log2 e)*s (scaling pre-folded into weights)
__device__ __forceinline__ float tanh_sp(float sp) {
    float t = ex2f(sp);
    float r = rcpf(1.0f + t);
    return fmaf(-2.0f, r, 1.0f);
}

__global__ void __launch_bounds__(256)
trm_kernel(const float* __restrict__ xs,
           const float* __restrict__ Wx,   const float* __restrict__ bx,
           const float* __restrict__ by,
           const float* __restrict__ Wnet, const float* __restrict__ bnet,
           const float* __restrict__ Wdec, const float* __restrict__ bdec,
           const float* __restrict__ Wq,   const float* __restrict__ bq,
           float* __restrict__ out, int rows)
{
    int i = blockIdx.x * blockDim.x + threadIdx.x;
    if (i >= rows) return;

    const float K = 2.8853900817779268f;  // 2 * log2(e)

    // ---- uniform weight loads (L1 broadcast), scaled by K ----
    float wy[4][4], wz[4][4], bn[4];
#pragma unroll
    for (int r = 0; r < 4; ++r)
#pragma unroll
        for (int c = 0; c < 4; ++c) {
            wy[r][c] = __ldg(&Wnet[(4 + r) * 4 + c]) * K;  // ye block
            wz[r][c] = __ldg(&Wnet[(8 + r) * 4 + c]) * K;  // z  block
        }
#pragma unroll
    for (int c = 0; c < 4; ++c) bn[c] = __ldg(&bnet[c]) * K;

    // ---- per-row invariants ----
    float2 x2 = reinterpret_cast<const float2*>(xs)[i];

    float xe[4];
#pragma unroll
    for (int c = 0; c < 4; ++c)
        xe[c] = fmaf(x2.x, __ldg(&Wx[c]), fmaf(x2.y, __ldg(&Wx[4 + c]), __ldg(&bx[c])));

    float prex[4];   // bn + xe . Wnet[0:4]  (scaled domain)
#pragma unroll
    for (int c = 0; c < 4; ++c) {
        float s = bn[c];
#pragma unroll
        for (int r = 0; r < 4; ++r)
            s = fmaf(xe[r], __ldg(&Wnet[r * 4 + c]) * K, s);
        prex[c] = s;
    }

    float ye[4], z[4];
#pragma unroll
    for (int c = 0; c < 4; ++c) { ye[c] = __ldg(&by[c]); z[c] = 0.0f; }

    // ---- main recursion: 16 outer, 6 z-steps + 1 y-step each ----
#pragma unroll 1
    for (int t = 0; t < T_ITERS; ++t) {
        float yep[4];
#pragma unroll
        for (int c = 0; c < 4; ++c) {
            float s = 0.0f;
#pragma unroll
            for (int r = 0; r < 4; ++r) s = fmaf(ye[r], wy[r][c], s);
            yep[c] = s;
        }
        float cz[4];
#pragma unroll
        for (int c = 0; c < 4; ++c) cz[c] = prex[c] + yep[c];

#pragma unroll
        for (int k = 0; k < N_ITERS; ++k) {
            float s[4];
#pragma unroll
            for (int c = 0; c < 4; ++c) {
                float a = cz[c];
#pragma unroll
                for (int r = 0; r < 4; ++r) a = fmaf(z[r], wz[r][c], a);
                s[c] = a;
            }
#pragma unroll
            for (int c = 0; c < 4; ++c) z[c] = tanh_sp(s[c]);
        }

        // y-step: step(zeros_xe, ye, z) -> uses bn + yep + z block
        float s[4];
#pragma unroll
        for (int c = 0; c < 4; ++c) {
            float a = bn[c] + yep[c];
#pragma unroll
            for (int r = 0; r < 4; ++r) a = fmaf(z[r], wz[r][c], a);
            s[c] = a;
        }
#pragma unroll
        for (int c = 0; c < 4; ++c) ye[c] = tanh_sp(s[c]);
    }

    // ---- decode heads ----
    float y = __ldg(&bdec[0]);
    float u = __ldg(&bq[0]);
#pragma unroll
    for (int r = 0; r < 4; ++r) {
        y = fmaf(ye[r], __ldg(&Wdec[r]), y);
        u = fmaf(ye[r], __ldg(&Wq[r]), u);
    }
    float q = rcpf(1.0f + ex2f(-1.4426950408889634f * u));  // sigmoid

    out[i]        = y;   // y_hat
    out[rows + i] = q;   // q_hat
}

extern "C" void kernel_launch(void* const* d_in, const int* in_sizes, int n_in,
                              void* d_out, int out_size)
{
    // metadata order: xs, Wx, bx, Wy, by, Wnet, bnet, Wdec, bdec, Wq, bq, T, n
    const float* xs   = (const float*)d_in[0];
    const float* Wx   = (const float*)d_in[1];
    const float* bx   = (const float*)d_in[2];
    // d_in[3] = Wy (dead: ys starts at zero)
    const float* by   = (const float*)d_in[4];
    const float* Wnet = (const float*)d_in[5];
    const float* bnet = (const float*)d_in[6];
    const float* Wdec = (const float*)d_in[7];
    const float* bdec = (const float*)d_in[8];
    const float* Wq   = (const float*)d_in[9];
    const float* bq   = (const float*)d_in[10];

    int rows = in_sizes[0] / 2;  // xs is [B, 2]
    float* out = (float*)d_out;

    int threads = 256;
    int blocks  = (rows + threads - 1) / threads;
    trm_kernel<<<blocks, threads>>>(xs, Wx, bx, by, Wnet, bnet,
                                    Wdec, bdec, Wq, bq, out, rows);
}

// round 6
// speedup vs baseline: 1.2676x; 1.2676x over previous
#include <cuda_runtime.h>
#include <cuda_bf16.h>

// TRM_57286273794231 — R3 (= R2 with compile fix).
// R1 measured 418.8us == exactly the MUFU floor at 8 MUFU/step (2 per tanh).
// This version: tanh.approx.f32 (1 MUFU per tanh -> halves the binding pipe)
// + fma.rn.f32x2 packed 4x4 matmuls (FMA pipe stays non-binding).

#define T_ITERS 16
#define N_ITERS 6

typedef unsigned long long ull_t;

__device__ __forceinline__ float tanh_fast(float x) {
    float r; asm("tanh.approx.f32 %0, %1;" : "=f"(r) : "f"(x)); return r;
}
__device__ __forceinline__ float ex2f(float x) {
    float r; asm("ex2.approx.f32 %0, %1;" : "=f"(r) : "f"(x)); return r;
}
__device__ __forceinline__ float rcpf(float x) {
    float r; asm("rcp.approx.f32 %0, %1;" : "=f"(r) : "f"(x)); return r;
}

__device__ __forceinline__ float2 fma2(float2 a, float2 b, float2 c) {
    ull_t ra = *reinterpret_cast<ull_t*>(&a);
    ull_t rb = *reinterpret_cast<ull_t*>(&b);
    ull_t rc = *reinterpret_cast<ull_t*>(&c);
    ull_t rd;
    asm("fma.rn.f32x2 %0, %1, %2, %3;" : "=l"(rd) : "l"(ra), "l"(rb), "l"(rc));
    return *reinterpret_cast<float2*>(&rd);
}
__device__ __forceinline__ float2 add2(float2 a, float2 b) {
    ull_t ra = *reinterpret_cast<ull_t*>(&a);
    ull_t rb = *reinterpret_cast<ull_t*>(&b);
    ull_t rd;
    asm("add.rn.f32x2 %0, %1, %2;" : "=l"(rd) : "l"(ra), "l"(rb));
    return *reinterpret_cast<float2*>(&rd);
}
__device__ __forceinline__ float2 bc2(float x) { return make_float2(x, x); }

__global__ void __launch_bounds__(256)
trm_kernel(const float* __restrict__ xs,
           const float* __restrict__ Wx,   const float* __restrict__ bx,
           const float* __restrict__ by,
           const float* __restrict__ Wnet, const float* __restrict__ bnet,
           const float* __restrict__ Wdec, const float* __restrict__ bdec,
           const float* __restrict__ Wq,   const float* __restrict__ bq,
           float* __restrict__ out, int rows)
{
    int i = blockIdx.x * blockDim.x + threadIdx.x;
    if (i >= rows) return;

    // ---- uniform weight loads, packed as column-pairs ----
    // wyA[r] = (Wnet[4+r][0], Wnet[4+r][1]),  wyB[r] = (.. [2], .. [3])
    float2 wyA[4], wyB[4], wzA[4], wzB[4];
#pragma unroll
    for (int r = 0; r < 4; ++r) {
        wyA[r] = make_float2(__ldg(&Wnet[(4 + r) * 4 + 0]), __ldg(&Wnet[(4 + r) * 4 + 1]));
        wyB[r] = make_float2(__ldg(&Wnet[(4 + r) * 4 + 2]), __ldg(&Wnet[(4 + r) * 4 + 3]));
        wzA[r] = make_float2(__ldg(&Wnet[(8 + r) * 4 + 0]), __ldg(&Wnet[(8 + r) * 4 + 1]));
        wzB[r] = make_float2(__ldg(&Wnet[(8 + r) * 4 + 2]), __ldg(&Wnet[(8 + r) * 4 + 3]));
    }
    float2 bnA = make_float2(__ldg(&bnet[0]), __ldg(&bnet[1]));
    float2 bnB = make_float2(__ldg(&bnet[2]), __ldg(&bnet[3]));

    // ---- per-row invariants ----
    float2 x2 = reinterpret_cast<const float2*>(xs)[i];

    float xe[4];
#pragma unroll
    for (int c = 0; c < 4; ++c)
        xe[c] = fmaf(x2.x, __ldg(&Wx[c]), fmaf(x2.y, __ldg(&Wx[4 + c]), __ldg(&bx[c])));

    // prexA/B = bn + xe . Wnet[0:4]   (per-row invariant)
    float2 prexA = bnA, prexB = bnB;
#pragma unroll
    for (int r = 0; r < 4; ++r) {
        float2 wA = make_float2(__ldg(&Wnet[r * 4 + 0]), __ldg(&Wnet[r * 4 + 1]));
        float2 wB = make_float2(__ldg(&Wnet[r * 4 + 2]), __ldg(&Wnet[r * 4 + 3]));
        prexA = fma2(bc2(xe[r]), wA, prexA);
        prexB = fma2(bc2(xe[r]), wB, prexB);
    }

    float ye[4], z[4];
#pragma unroll
    for (int c = 0; c < 4; ++c) { ye[c] = __ldg(&by[c]); z[c] = 0.0f; }

    // ---- main recursion ----
#pragma unroll 1
    for (int t = 0; t < T_ITERS; ++t) {
        // yep = ye . Wnet[4:8]  (invariant over the 6 z-steps)
        float2 yepA = make_float2(0.f, 0.f), yepB = make_float2(0.f, 0.f);
#pragma unroll
        for (int r = 0; r < 4; ++r) {
            float2 b = bc2(ye[r]);
            yepA = fma2(b, wyA[r], yepA);
            yepB = fma2(b, wyB[r], yepB);
        }
        float2 czA = add2(prexA, yepA);   // z-step constant (with xe)
        float2 czB = add2(prexB, yepB);

#pragma unroll
        for (int k = 0; k < N_ITERS; ++k) {
            float2 sA = czA, sB = czB;
#pragma unroll
            for (int r = 0; r < 4; ++r) {
                float2 b = bc2(z[r]);
                sA = fma2(b, wzA[r], sA);
                sB = fma2(b, wzB[r], sB);
            }
            z[0] = tanh_fast(sA.x); z[1] = tanh_fast(sA.y);
            z[2] = tanh_fast(sB.x); z[3] = tanh_fast(sB.y);
        }

        // y-step: step(zeros_xe, ye, z) -> bn + yep + z block
        float2 sA = add2(bnA, yepA);
        float2 sB = add2(bnB, yepB);
#pragma unroll
        for (int r = 0; r < 4; ++r) {
            float2 b = bc2(z[r]);
            sA = fma2(b, wzA[r], sA);
            sB = fma2(b, wzB[r], sB);
        }
        ye[0] = tanh_fast(sA.x); ye[1] = tanh_fast(sA.y);
        ye[2] = tanh_fast(sB.x); ye[3] = tanh_fast(sB.y);
    }

    // ---- decode heads (full precision) ----
    float y = __ldg(&bdec[0]);
    float u = __ldg(&bq[0]);
#pragma unroll
    for (int r = 0; r < 4; ++r) {
        y = fmaf(ye[r], __ldg(&Wdec[r]), y);
        u = fmaf(ye[r], __ldg(&Wq[r]), u);
    }
    float q = rcpf(1.0f + ex2f(-1.4426950408889634f * u));  // sigmoid

    out[i]        = y;   // y_hat
    out[rows + i] = q;   // q_hat
}

extern "C" void kernel_launch(void* const* d_in, const int* in_sizes, int n_in,
                              void* d_out, int out_size)
{
    // metadata order: xs, Wx, bx, Wy, by, Wnet, bnet, Wdec, bdec, Wq, bq, T, n
    const float* xs   = (const float*)d_in[0];
    const float* Wx   = (const float*)d_in[1];
    const float* bx   = (const float*)d_in[2];
    // d_in[3] = Wy (dead: ys starts at zero)
    const float* by   = (const float*)d_in[4];
    const float* Wnet = (const float*)d_in[5];
    const float* bnet = (const float*)d_in[6];
    const float* Wdec = (const float*)d_in[7];
    const float* bdec = (const float*)d_in[8];
    const float* Wq   = (const float*)d_in[9];
    const float* bq   = (const float*)d_in[10];

    int rows = in_sizes[0] / 2;  // xs is [B, 2]
    float* out = (float*)d_out;

    int threads = 256;
    int blocks  = (rows + threads - 1) / threads;
    trm_kernel<<<blocks, threads>>>(xs, Wx, bx, by, Wnet, bnet,
                                    Wdec, bdec, Wq, bq, out, rows);
}